// round 17
// baseline (speedup 1.0000x reference)
#include <cuda_runtime.h>

#define ZPL    8
#define ROI    20
#define NPX    400
#define SPL_D  64
#define SPL_H  40
#define SPL_W  40
#define SVP    129    // sval pitch (words): (lane + e) distinct banks

typedef unsigned long long u64;

__device__ __forceinline__ u64 ffma2(u64 a, u64 b, u64 c) {
    u64 d;
    asm("fma.rn.f32x2 %0, %1, %2, %3;" : "=l"(d) : "l"(a), "l"(b), "l"(c));
    return d;
}
__device__ __forceinline__ u64 fmul2(u64 a, u64 b) {
    u64 d;
    asm("mul.rn.f32x2 %0, %1, %2;" : "=l"(d) : "l"(a), "l"(b));
    return d;
}
__device__ __forceinline__ u64 fpack2(float lo, float hi) {
    u64 d;
    asm("mov.b64 %0, {%1, %2};" : "=l"(d) : "f"(lo), "f"(hi));
    return d;
}
__device__ __forceinline__ float fhadd2(u64 a) {
    float lo, hi;
    asm("mov.b64 {%0, %1}, %2;" : "=f"(lo), "=f"(hi) : "l"(a));
    return lo + hi;
}

// Partial coefficient sums: g_csumq[(z*16+g)*64 + t], g = group of 25 cells.
__device__ float g_csumq[ZPL * 16 * 64];

// Kernel 1: 128 blocks x 64 threads, deterministic partials.
__global__ __launch_bounds__(64) void csum_kernel(const float* __restrict__ coefs)
{
    const int z = blockIdx.x >> 4, g = blockIdx.x & 15, t = threadIdx.x;
    const float* gbase = coefs + ((((size_t)(z + 27) * SPL_H + 9) * SPL_W + 9) << 6);
    float s = 0.0f;
    #pragma unroll 5
    for (int r = 0; r < 25; r++) {
        int P = g * 25 + r;
        int y = P / 20, x = P - y * 20;
        s += gbase[((y * SPL_W + x) << 6) + t];
    }
    g_csumq[(z * 16 + g) * 64 + t] = s;
}

// Kernel 2: block = (echunk4 x pxg16 x z8) -> grid 512 x 128 threads.
// lane/thread = emitter (128 per block); block covers 25 pixels of one z-plane.
__global__ __launch_bounds__(128) void psf_main(
    const float* __restrict__ pos,
    const float* __restrict__ inten,
    const float* __restrict__ bg,
    const float* __restrict__ coefs,
    float* __restrict__ out)
{
    __shared__ float sC[25 * 64];        // 6.4 KB staged cells (cell-major)
    __shared__ float sval[25 * SVP];     // scaled outputs [px][em]
    __shared__ float sCsum[64];

    const int ech = blockIdx.x & 3;
    const int pxg = (blockIdx.x >> 2) & 15;
    const int z   = blockIdx.x >> 6;
    const int tid = threadIdx.x;
    const int e   = ech * 128 + tid;
    const int p0px = pxg * 25;

    const float* gbase = coefs + ((((size_t)(z + 27) * SPL_H + 9) * SPL_W + 9) << 6);

    // ---- Stage 25 cells (400 float4, coalesced) ----
    #pragma unroll
    for (int k = 0; k < 4; k++) {
        int i = tid + k * 128;
        if (i < 400) {
            int c = i >> 4, comp = i & 15;
            int P = p0px + c;
            int y = P / 20, x = P - y * 20;
            ((float4*)sC)[i] =
                *(const float4*)(gbase + ((y * SPL_W + x) << 6) + comp * 4);
        }
    }
    // ---- Combine Csum partials (threads 0..63) ----
    if (tid < 64) {
        float s = 0.0f;
        #pragma unroll
        for (int g = 0; g < 16; g++) s += g_csumq[(z * 16 + g) * 64 + tid];
        sCsum[tid] = s;
    }

    // ---- Per-emitter params (exact reference expressions) ----
    const float pp0 = pos[e * 3 + 0];   // Y axis (faithful to reference)
    const float pp1 = pos[e * 3 + 1];   // X axis
    const float pp2 = pos[e * 3 + 2];   // Z axis

    float pzf = (float)z - pp2 + 28.0f;            // SPL_D/2 - ZPL/2
    float fz  = floorf(pzf);
    float dzv = pzf - fz;
    int   iz  = max(0, min((int)fz, SPL_D - 1));

    float py0 = (0.0f - pp0) + 10.0f;              // SPL_H/2 - ROI/2
    float fy0 = floorf(py0);
    float dyv = py0 - fy0;
    int   iy0 = (int)fy0;

    float px0 = (0.0f - pp1) + 10.0f;              // SPL_W/2 - ROI/2
    float fx0 = floorf(px0);
    float dxv = px0 - fx0;
    int   ix0 = (int)fx0;

    bool ok = (iy0 == 9) && (ix0 == 9) && (iz == z + 27);
    #pragma unroll
    for (int qq = 1; qq < ROI; qq++) {
        ok &= floorf(((float)qq - pp0) + 10.0f) == (float)(iy0 + qq);
        ok &= floorf(((float)qq - pp1) + 10.0f) == (float)(ix0 + qq);
    }

    __syncthreads();

    if (ok) {
        // ---- Scale via Csum identity (factorized, thread-local) ----
        float dx2 = dxv * dxv, dx3 = dx2 * dxv;
        float dy2 = dyv * dyv, dy3 = dy2 * dyv;
        float dz2 = dzv * dzv, dz3 = dz2 * dzv;
        float xp[4] = {1.0f, dxv, dx2, dx3};
        float yp[4] = {1.0f, dyv, dy2, dy3};
        float zp[4] = {1.0f, dzv, dz2, dz3};
        float tot = 0.0f;
        #pragma unroll
        for (int a = 0; a < 4; a++) {
            float ta = 0.0f;
            #pragma unroll
            for (int b = 0; b < 4; b++) {
                const float* cs = sCsum + (a * 4 + b) * 4;
                float sb = fmaf(xp[3], cs[3], fmaf(xp[2], cs[2],
                           fmaf(xp[1], cs[1], cs[0])));
                ta = fmaf(yp[b], sb, ta);
            }
            tot = fmaf(zp[a], ta, tot);
        }
        const float scale = inten[e * ZPL + z] / tot;
        const float bgv   = bg[e * ZPL + z];

        // ---- Packed weights (R10-verified layout) ----
        const u64 q01 = fpack2(1.0f, dxv);
        const u64 q23 = fpack2(dx2, dx3);
        u64 Wb[4][2];
        Wb[0][0] = q01;               Wb[0][1] = q23;
        u64 yd1 = fpack2(dyv, dyv);   Wb[1][0] = fmul2(q01, yd1); Wb[1][1] = fmul2(q23, yd1);
        u64 yd2 = fpack2(dy2, dy2);   Wb[2][0] = fmul2(q01, yd2); Wb[2][1] = fmul2(q23, yd2);
        u64 yd3 = fpack2(dy3, dy3);   Wb[3][0] = fmul2(q01, yd3); Wb[3][1] = fmul2(q23, yd3);
        const u64 dzp  = fpack2(dzv, dzv);
        const u64 dz2p = fpack2(dz2, dz2);
        const u64 dz3p = fpack2(dz3, dz3);

        // ---- 12 pixel-pairs + 1, LDS broadcast reads of staged cells ----
        #pragma unroll 3
        for (int pr = 0; pr < 12; pr++) {
            const int pA = pr * 2, pB = pA + 1;
            const ulonglong2* cpA = (const ulonglong2*)(sC + pA * 64);
            const ulonglong2* cpB = (const ulonglong2*)(sC + pB * 64);

            u64 aA0 = 0, aA1 = 0, aA2 = 0, aA3 = 0;
            u64 aB0 = 0, aB1 = 0, aB2 = 0, aB3 = 0;
            #pragma unroll
            for (int bq = 0; bq < 4; bq++) {
                ulonglong2 A0 = cpA[ 0 + bq];
                ulonglong2 A1 = cpA[ 4 + bq];
                ulonglong2 A2 = cpA[ 8 + bq];
                ulonglong2 A3 = cpA[12 + bq];
                ulonglong2 B0 = cpB[ 0 + bq];
                ulonglong2 B1 = cpB[ 4 + bq];
                ulonglong2 B2 = cpB[ 8 + bq];
                ulonglong2 B3 = cpB[12 + bq];
                aA0 = ffma2(A0.x, Wb[bq][0], aA0);
                aA1 = ffma2(A1.x, Wb[bq][0], aA1);
                aA2 = ffma2(A2.x, Wb[bq][0], aA2);
                aA3 = ffma2(A3.x, Wb[bq][0], aA3);
                aB0 = ffma2(B0.x, Wb[bq][0], aB0);
                aB1 = ffma2(B1.x, Wb[bq][0], aB1);
                aB2 = ffma2(B2.x, Wb[bq][0], aB2);
                aB3 = ffma2(B3.x, Wb[bq][0], aB3);
                aA0 = ffma2(A0.y, Wb[bq][1], aA0);
                aA1 = ffma2(A1.y, Wb[bq][1], aA1);
                aA2 = ffma2(A2.y, Wb[bq][1], aA2);
                aA3 = ffma2(A3.y, Wb[bq][1], aA3);
                aB0 = ffma2(B0.y, Wb[bq][1], aB0);
                aB1 = ffma2(B1.y, Wb[bq][1], aB1);
                aB2 = ffma2(B2.y, Wb[bq][1], aB2);
                aB3 = ffma2(B3.y, Wb[bq][1], aB3);
            }
            u64 mA = ffma2(aA1, dzp, aA0);
            u64 mB = ffma2(aB1, dzp, aB0);
            mA = ffma2(aA2, dz2p, mA);
            mB = ffma2(aB2, dz2p, mB);
            mA = ffma2(aA3, dz3p, mA);
            mB = ffma2(aB3, dz3p, mB);
            sval[pA * SVP + tid] = fmaf(fhadd2(mA), scale, bgv);
            sval[pB * SVP + tid] = fmaf(fhadd2(mB), scale, bgv);
        }
        {   // leftover pixel 24
            const ulonglong2* cp = (const ulonglong2*)(sC + 24 * 64);
            u64 a0 = 0, a1 = 0, a2 = 0, a3 = 0;
            #pragma unroll
            for (int bq = 0; bq < 4; bq++) {
                ulonglong2 v0 = cp[ 0 + bq];
                ulonglong2 v1 = cp[ 4 + bq];
                ulonglong2 v2 = cp[ 8 + bq];
                ulonglong2 v3 = cp[12 + bq];
                a0 = ffma2(v0.x, Wb[bq][0], a0);
                a1 = ffma2(v1.x, Wb[bq][0], a1);
                a2 = ffma2(v2.x, Wb[bq][0], a2);
                a3 = ffma2(v3.x, Wb[bq][0], a3);
                a0 = ffma2(v0.y, Wb[bq][1], a0);
                a1 = ffma2(v1.y, Wb[bq][1], a1);
                a2 = ffma2(v2.y, Wb[bq][1], a2);
                a3 = ffma2(v3.y, Wb[bq][1], a3);
            }
            u64 m = ffma2(a1, dzp, a0);
            m = ffma2(a2, dz2p, m);
            m = ffma2(a3, dz3p, m);
            sval[24 * SVP + tid] = fmaf(fhadd2(m), scale, bgv);
        }
    } else {
        // ---- EXACT FALLBACK (bit-faithful per pixel; thread-local) ----
        const int izoff = iz * SPL_H;
        float dz2 = dzv * dzv, dz3 = dz2 * dzv;
        float tot = 0.0f;
        for (int P = 0; P < NPX; P++) {
            const int y = P / 20, x = P - y * 20;
            float pyf = (float)y - pp0 + 10.0f;
            float fy  = floorf(pyf);
            float dyy = pyf - fy;
            int   iy  = max(0, min((int)fy, SPL_H - 1));
            float pxf = (float)x - pp1 + 10.0f;
            float fx  = floorf(pxf);
            float dxx = pxf - fx;
            int   ix  = max(0, min((int)fx, SPL_W - 1));
            float dxx2 = dxx * dxx, dxx3 = dxx2 * dxx;
            float dyy2 = dyy * dyy, dyy3 = dyy2 * dyy;
            const float4* cp = (const float4*)(coefs +
                (((size_t)(izoff + iy) * SPL_W + ix) << 6));
            float s[4];
            #pragma unroll
            for (int a = 0; a < 4; a++) {
                float4 c0 = cp[a*4+0], c1 = cp[a*4+1], c2 = cp[a*4+2], c3 = cp[a*4+3];
                float t0 = fmaf(c0.w, dxx3, fmaf(c0.z, dxx2, fmaf(c0.y, dxx, c0.x)));
                float t1 = fmaf(c1.w, dxx3, fmaf(c1.z, dxx2, fmaf(c1.y, dxx, c1.x)));
                float t2 = fmaf(c2.w, dxx3, fmaf(c2.z, dxx2, fmaf(c2.y, dxx, c2.x)));
                float t3 = fmaf(c3.w, dxx3, fmaf(c3.z, dxx2, fmaf(c3.y, dxx, c3.x)));
                s[a] = fmaf(t3, dyy3, fmaf(t2, dyy2, fmaf(t1, dyy, t0)));
            }
            float v = fmaf(s[3], dz3, fmaf(s[2], dz2, fmaf(s[1], dzv, s[0])));
            tot += v;
            int lp = P - p0px;
            if (lp >= 0 && lp < 25) sval[lp * SVP + tid] = v;   // raw for now
        }
        const float scale = inten[e * ZPL + z] / tot;
        const float bgv   = bg[e * ZPL + z];
        #pragma unroll
        for (int i = 0; i < 25; i++)
            sval[i * SVP + tid] = fmaf(sval[i * SVP + tid], scale, bgv);
    }

    __syncthreads();

    // ---- Epilogue: warp w writes emitters w*32..w*32+31 (pure copy) ----
    {
        const int w    = tid >> 5;
        const int lane = tid & 31;
        #pragma unroll 4
        for (int k = 0; k < 32; k++) {
            const int el = w * 32 + k;
            if (lane < 25) {
                float v = sval[lane * SVP + el];    // conflict-free (pitch 129)
                out[((size_t)(ech * 128 + el) * ZPL + z) * NPX + p0px + lane] = v;
            }
        }
    }
}

extern "C" void kernel_launch(void* const* d_in, const int* in_sizes, int n_in,
                              void* d_out, int out_size)
{
    const float* pos   = (const float*)d_in[0];
    const float* inten = (const float*)d_in[1];
    const float* bg    = (const float*)d_in[2];
    const float* coefs = (const float*)d_in[3];

    csum_kernel<<<128, 64>>>(coefs);
    psf_main<<<512, 128>>>(pos, inten, bg, coefs, (float*)d_out);
}